// round 7
// baseline (speedup 1.0000x reference)
#include <cuda_runtime.h>
#include <cuda_fp16.h>
#include <cstdint>

// Problem: qkv (2, 2048, 3, 32, 128) fp32, causal=1, out (2,2048,32,128) fp32
#define Bb 2
#define Ss 2048
#define Hh 32
#define DH 128

#define BM 64           // query rows per CTA (4 warps x 16 rows)
#define BN 64           // key rows per tile
#define KS 136          // fp16 smem row stride in halves (272B: conflict-free ldmatrix)
#define NSTAGE 3
#define STAGE_H (2 * BN * KS)     // halves per stage (K tile + V tile)

// fp16 copies of K and V, head-major: [kv][b][h][s][d] -> tiles are contiguous
__device__ __half g_kvh[(size_t)2 * Bb * Hh * Ss * DH];

__device__ __forceinline__ uint32_t s2u(const void* p) {
    return (uint32_t)__cvta_generic_to_shared(p);
}

__device__ __forceinline__ void cp_async16(uint32_t dst, const void* src) {
    asm volatile("cp.async.cg.shared.global [%0],[%1],16;" :: "r"(dst), "l"(src));
}

__device__ __forceinline__ void cp_commit() {
    asm volatile("cp.async.commit_group;");
}

template <int N>
__device__ __forceinline__ void cp_wait() {
    asm volatile("cp.async.wait_group %0;" :: "n"(N));
}

__device__ __forceinline__ uint32_t packh2(float a, float b) {
    __half2 h = __floats2half2_rn(a, b);
    return *(uint32_t*)&h;
}

__device__ __forceinline__ void mma16816(float& c0, float& c1, float& c2, float& c3,
                                         uint32_t a0, uint32_t a1, uint32_t a2, uint32_t a3,
                                         uint32_t b0, uint32_t b1) {
    asm volatile(
        "mma.sync.aligned.m16n8k16.row.col.f32.f16.f16.f32 "
        "{%0,%1,%2,%3},{%4,%5,%6,%7},{%8,%9},{%0,%1,%2,%3};"
        : "+f"(c0), "+f"(c1), "+f"(c2), "+f"(c3)
        : "r"(a0), "r"(a1), "r"(a2), "r"(a3), "r"(b0), "r"(b1));
}

__device__ __forceinline__ void ldsm4(uint32_t& r0, uint32_t& r1, uint32_t& r2, uint32_t& r3,
                                      uint32_t addr) {
    asm volatile("ldmatrix.sync.aligned.m8n8.x4.shared.b16 {%0,%1,%2,%3},[%4];"
                 : "=r"(r0), "=r"(r1), "=r"(r2), "=r"(r3) : "r"(addr));
}

__device__ __forceinline__ void ldsm4t(uint32_t& r0, uint32_t& r1, uint32_t& r2, uint32_t& r3,
                                       uint32_t addr) {
    asm volatile("ldmatrix.sync.aligned.m8n8.x4.trans.shared.b16 {%0,%1,%2,%3},[%4];"
                 : "=r"(r0), "=r"(r1), "=r"(r2), "=r"(r3) : "r"(addr));
}

// ---------------- pre-pass: fp32 K/V -> fp16 head-major copy ----------------
__global__ __launch_bounds__(256) void cvt_kv_kernel(const float* __restrict__ qkv) {
    int gid = blockIdx.x * 256 + threadIdx.x;     // one thread = 8 elements
    int d8   = gid & 15;
    int rest = gid >> 4;
    int s    = rest & (Ss - 1);
    int r2   = rest >> 11;
    int h    = r2 & (Hh - 1);
    int r3   = r2 >> 5;
    int b    = r3 & (Bb - 1);
    int kv   = r3 >> 1;

    const float* src = qkv + (((size_t)(b * Ss + s) * 3 + 1 + kv) * Hh + h) * DH + d8 * 8;
    float4 x0 = ((const float4*)src)[0];
    float4 x1 = ((const float4*)src)[1];
    uint4 o;
    o.x = packh2(x0.x, x0.y);
    o.y = packh2(x0.z, x0.w);
    o.z = packh2(x1.x, x1.y);
    o.w = packh2(x1.z, x1.w);
    __half* dst = g_kvh + (((size_t)(kv * Bb + b) * Hh + h) * Ss + s) * DH + d8 * 8;
    *(uint4*)dst = o;
}

// ---------------- main attention kernel: 128 threads, 2 CTAs/SM ----------------
extern __shared__ __align__(16) __half smem_h[];

__global__ __launch_bounds__(128) void fa_f16_kernel(const float* __restrict__ qkv,
                                                     float* __restrict__ out) {
    const int iq   = gridDim.x - 1 - blockIdx.x;   // largest causal span first
    const int bh   = blockIdx.y;
    const int b    = bh >> 5;
    const int h    = bh & 31;
    const int tid  = threadIdx.x;
    const int warp = tid >> 5;
    const int lane = tid & 31;
    const int lr   = lane >> 2;          // 0..7
    const int lc   = lane & 3;           // 0..3
    const int lm   = lane >> 3;          // ldmatrix matrix id 0..3
    const int lx   = lane & 7;           // ldmatrix row-in-matrix

    const float scale = 0.08838834764831845f;   // 1/sqrt(128)
    const int HD = Hh * DH;

    const int rowmin = iq * BM + warp * 16;
    const int qr0 = rowmin + lr;
    const int qr1 = qr0 + 8;
    const int jmax = iq;                 // BM == BN: diagonal tile is j == iq

    const __half* kvb_k = g_kvh + ((size_t)(0 * Bb + b) * Hh + h) * Ss * DH;
    const __half* kvb_v = g_kvh + ((size_t)(1 * Bb + b) * Hh + h) * Ss * DH;

    // cp.async mapping (128 threads): thread -> (row, half-row of 8 x 16B chunks)
    const int crow = tid >> 1;            // 0..63
    const int chalf = (tid & 1) * 64;     // halves offset (0 or 64 within 128-half row)

    auto issue_tile = [&](int jj) {
        const __half* kt = kvb_k + (size_t)jj * BN * DH + crow * DH + chalf;
        const __half* vt = kvb_v + (size_t)jj * BN * DH + crow * DH + chalf;
        __half* st = smem_h + (jj % NSTAGE) * STAGE_H + crow * KS + chalf;
        uint32_t dK = s2u(st);
        uint32_t dV = dK + BN * KS * 2u;
#pragma unroll
        for (int i = 0; i < 8; i++) {
            cp_async16(dK + i * 16, kt + i * 8);
            cp_async16(dV + i * 16, vt + i * 8);
        }
    };

    // ---- prologue: tiles 0 and 1 in flight (always 2 commit groups) ----
    issue_tile(0);
    cp_commit();
    if (jmax >= 1) issue_tile(1);
    cp_commit();

    // ---- Q fragments (fp16, scale folded): 8 k-blocks x 4 regs ----
    uint32_t qf[8][4];
    {
        const float* q0 = qkv + ((size_t)(b * Ss + qr0) * 3) * HD + h * DH;
        const float* q1 = qkv + ((size_t)(b * Ss + qr1) * 3) * HD + h * DH;
#pragma unroll
        for (int kb = 0; kb < 8; kb++) {
            int d = kb * 16 + 2 * lc;
            float2 x0 = *(const float2*)(q0 + d);
            float2 x1 = *(const float2*)(q1 + d);
            float2 x2 = *(const float2*)(q0 + d + 8);
            float2 x3 = *(const float2*)(q1 + d + 8);
            qf[kb][0] = packh2(x0.x * scale, x0.y * scale);
            qf[kb][1] = packh2(x1.x * scale, x1.y * scale);
            qf[kb][2] = packh2(x2.x * scale, x2.y * scale);
            qf[kb][3] = packh2(x3.x * scale, x3.y * scale);
        }
    }

    float O[16][4];
#pragma unroll
    for (int n = 0; n < 16; n++) { O[n][0] = 0.f; O[n][1] = 0.f; O[n][2] = 0.f; O[n][3] = 0.f; }
    float m0 = -1e30f, m1 = -1e30f, l0 = 0.f, l1 = 0.f;

    for (int j = 0; j <= jmax; j++) {
        // retire tile j (leave tile j+1's group outstanding)
        cp_wait<1>();
        __syncthreads();                  // all warps done with stage (j-1)%NSTAGE; data of j visible
        // issue tile j+2 into stage (j+2)%NSTAGE == (j-1)%NSTAGE — safe after the barrier
        if (j + 2 <= jmax) issue_tile(j + 2);
        cp_commit();

        const __half* Ks = smem_h + (j % NSTAGE) * STAGE_H;
        const uint32_t kbase = s2u(Ks);
        const uint32_t vbase = kbase + BN * KS * 2u;

        // ---- S = Q K^T ----
        float sacc[8][4];
#pragma unroll
        for (int n = 0; n < 8; n++) { sacc[n][0] = 0.f; sacc[n][1] = 0.f; sacc[n][2] = 0.f; sacc[n][3] = 0.f; }
#pragma unroll
        for (int kb = 0; kb < 8; kb++) {
#pragma unroll
            for (int nbp = 0; nbp < 4; nbp++) {
                int key = nbp * 16 + (lm >> 1) * 8 + lx;
                int dim = kb * 16 + (lm & 1) * 8;
                uint32_t r0, r1, r2, r3;
                ldsm4(r0, r1, r2, r3, kbase + (uint32_t)(key * KS + dim) * 2u);
                mma16816(sacc[2*nbp][0], sacc[2*nbp][1], sacc[2*nbp][2], sacc[2*nbp][3],
                         qf[kb][0], qf[kb][1], qf[kb][2], qf[kb][3], r0, r1);
                mma16816(sacc[2*nbp+1][0], sacc[2*nbp+1][1], sacc[2*nbp+1][2], sacc[2*nbp+1][3],
                         qf[kb][0], qf[kb][1], qf[kb][2], qf[kb][3], r2, r3);
            }
        }

        // ---- causal mask (diagonal tile only) ----
        if ((j + 1) * BN - 1 > rowmin) {
#pragma unroll
            for (int n = 0; n < 8; n++) {
                int col = j * BN + n * 8 + 2 * lc;
                if (col     > qr0) sacc[n][0] = -1e30f;
                if (col + 1 > qr0) sacc[n][1] = -1e30f;
                if (col     > qr1) sacc[n][2] = -1e30f;
                if (col + 1 > qr1) sacc[n][3] = -1e30f;
            }
        }

        // ---- online softmax ----
        float tm0 = -1e30f, tm1 = -1e30f;
#pragma unroll
        for (int n = 0; n < 8; n++) {
            tm0 = fmaxf(tm0, fmaxf(sacc[n][0], sacc[n][1]));
            tm1 = fmaxf(tm1, fmaxf(sacc[n][2], sacc[n][3]));
        }
        tm0 = fmaxf(tm0, __shfl_xor_sync(0xffffffffu, tm0, 1));
        tm0 = fmaxf(tm0, __shfl_xor_sync(0xffffffffu, tm0, 2));
        tm1 = fmaxf(tm1, __shfl_xor_sync(0xffffffffu, tm1, 1));
        tm1 = fmaxf(tm1, __shfl_xor_sync(0xffffffffu, tm1, 2));

        float mn0 = fmaxf(m0, tm0);
        float mn1 = fmaxf(m1, tm1);
        bool  need = (mn0 > m0) || (mn1 > m1);
        float al0 = __expf(m0 - mn0);
        float al1 = __expf(m1 - mn1);

        float rs0 = 0.f, rs1 = 0.f;
        uint32_t pf[4][4];     // P as A-fragments
#pragma unroll
        for (int t = 0; t < 4; t++) {
            int n0 = 2 * t, n1 = 2 * t + 1;
            float e00 = __expf(sacc[n0][0] - mn0);
            float e01 = __expf(sacc[n0][1] - mn0);
            float e02 = __expf(sacc[n0][2] - mn1);
            float e03 = __expf(sacc[n0][3] - mn1);
            float e10 = __expf(sacc[n1][0] - mn0);
            float e11 = __expf(sacc[n1][1] - mn0);
            float e12 = __expf(sacc[n1][2] - mn1);
            float e13 = __expf(sacc[n1][3] - mn1);
            rs0 += e00 + e01 + e10 + e11;
            rs1 += e02 + e03 + e12 + e13;
            pf[t][0] = packh2(e00, e01);
            pf[t][1] = packh2(e02, e03);
            pf[t][2] = packh2(e10, e11);
            pf[t][3] = packh2(e12, e13);
        }
        rs0 += __shfl_xor_sync(0xffffffffu, rs0, 1);
        rs0 += __shfl_xor_sync(0xffffffffu, rs0, 2);
        rs1 += __shfl_xor_sync(0xffffffffu, rs1, 1);
        rs1 += __shfl_xor_sync(0xffffffffu, rs1, 2);

        l0 = l0 * al0 + rs0;
        l1 = l1 * al1 + rs1;
        m0 = mn0;
        m1 = mn1;

        // rescale O only if the running max actually moved (exp(0)==1 exactly)
        if (__any_sync(0xffffffffu, need)) {
#pragma unroll
            for (int n = 0; n < 16; n++) {
                O[n][0] *= al0; O[n][1] *= al0;
                O[n][2] *= al1; O[n][3] *= al1;
            }
        }

        // ---- O += P V (ldmatrix.trans) ----
#pragma unroll
        for (int kbv = 0; kbv < 4; kbv++) {
#pragma unroll
            for (int nbp = 0; nbp < 8; nbp++) {
                int key = kbv * 16 + (lm & 1) * 8 + lx;
                int dim = nbp * 16 + (lm >> 1) * 8;
                uint32_t r0, r1, r2, r3;
                ldsm4t(r0, r1, r2, r3, vbase + (uint32_t)(key * KS + dim) * 2u);
                mma16816(O[2*nbp][0], O[2*nbp][1], O[2*nbp][2], O[2*nbp][3],
                         pf[kbv][0], pf[kbv][1], pf[kbv][2], pf[kbv][3], r0, r1);
                mma16816(O[2*nbp+1][0], O[2*nbp+1][1], O[2*nbp+1][2], O[2*nbp+1][3],
                         pf[kbv][0], pf[kbv][1], pf[kbv][2], pf[kbv][3], r2, r3);
            }
        }
    }

    // ---- epilogue ----
    float inv0 = 1.f / l0;
    float inv1 = 1.f / l1;
    float* ob0 = out + ((size_t)(b * Ss + qr0) * Hh + h) * DH;
    float* ob1 = out + ((size_t)(b * Ss + qr1) * Hh + h) * DH;
#pragma unroll
    for (int n = 0; n < 16; n++) {
        int d = n * 8 + 2 * lc;
        *(float2*)(ob0 + d) = make_float2(O[n][0] * inv0, O[n][1] * inv0);
        *(float2*)(ob1 + d) = make_float2(O[n][2] * inv1, O[n][3] * inv1);
    }
}

extern "C" void kernel_launch(void* const* d_in, const int* in_sizes, int n_in,
                              void* d_out, int out_size) {
    const float* qkv = (const float*)d_in[0];
    (void)in_sizes; (void)n_in; (void)out_size;

    // pre-pass: 2*Bb*Hh*Ss*(DH/8) threads
    int cvt_blocks = (2 * Bb * Hh * Ss * (DH / 8)) / 256;   // 16384
    cvt_kv_kernel<<<cvt_blocks, 256>>>(qkv);

    const size_t smem_bytes = (size_t)NSTAGE * STAGE_H * sizeof(__half);   // 104448
    cudaFuncSetAttribute(fa_f16_kernel, cudaFuncAttributeMaxDynamicSharedMemorySize,
                         (int)smem_bytes);

    dim3 grid(Ss / BM, Bb * Hh);   // (32, 64)
    fa_f16_kernel<<<grid, 128, smem_bytes>>>(qkv, (float*)d_out);
}

// round 9
// speedup vs baseline: 1.8264x; 1.8264x over previous
#include <cuda_runtime.h>
#include <cuda_fp16.h>
#include <cstdint>

// Problem: qkv (2, 2048, 3, 32, 128) fp32, causal=1, out (2,2048,32,128) fp32
#define Bb 2
#define Ss 2048
#define Hh 32
#define DH 128

#define BM 128              // query rows per CTA (8 compute warps x 16 rows)
#define BN 64               // key rows per tile
#define KS 136              // fp16 smem row stride in halves
#define NSTAGE 4
#define VOFF_B (BN * KS * 2)            // V offset within a stage (bytes)
#define STAGE_B (2 * BN * KS * 2)       // stage size in bytes (34816)
#define BAR_OFF (NSTAGE * STAGE_B)      // barriers after the ring (bytes)

// fp16 copies of K and V, head-major: [kv][b][h][s][d]
__device__ __half g_kvh[(size_t)2 * Bb * Hh * Ss * DH];

__device__ __forceinline__ uint32_t s2u(const void* p) {
    return (uint32_t)__cvta_generic_to_shared(p);
}
__device__ __forceinline__ void cp16(uint32_t dst, const void* src) {
    asm volatile("cp.async.cg.shared.global [%0],[%1],16;" :: "r"(dst), "l"(src));
}
__device__ __forceinline__ void cp_commit() {
    asm volatile("cp.async.commit_group;");
}
template <int N>
__device__ __forceinline__ void cp_wait() {
    asm volatile("cp.async.wait_group %0;" :: "n"(N));
}
__device__ __forceinline__ uint32_t packh2(float a, float b) {
    __half2 h = __floats2half2_rn(a, b);
    return *(uint32_t*)&h;
}
__device__ __forceinline__ float ex2f(float x) {
    float y;
    asm("ex2.approx.ftz.f32 %0, %1;" : "=f"(y) : "f"(x));
    return y;
}
__device__ __forceinline__ void mbar_init(uint32_t a, uint32_t n) {
    asm volatile("mbarrier.init.shared.b64 [%0], %1;" :: "r"(a), "r"(n) : "memory");
}
__device__ __forceinline__ void mbar_arrive(uint32_t a) {
    asm volatile("mbarrier.arrive.shared.b64 _, [%0];" :: "r"(a) : "memory");
}
__device__ __forceinline__ void mbar_wait(uint32_t a, uint32_t ph) {
    asm volatile(
        "{\n\t.reg .pred P;\n\t"
        "WL%=:\n\t"
        "mbarrier.try_wait.parity.acquire.cta.shared::cta.b64 P, [%0], %1, 0x989680;\n\t"
        "@P bra WD%=;\n\t"
        "bra WL%=;\n\t"
        "WD%=:\n\t}"
        :: "r"(a), "r"(ph) : "memory");
}
__device__ __forceinline__ void mma16816(float& c0, float& c1, float& c2, float& c3,
                                         uint32_t a0, uint32_t a1, uint32_t a2, uint32_t a3,
                                         uint32_t b0, uint32_t b1) {
    asm volatile(
        "mma.sync.aligned.m16n8k16.row.col.f32.f16.f16.f32 "
        "{%0,%1,%2,%3},{%4,%5,%6,%7},{%8,%9},{%0,%1,%2,%3};"
        : "+f"(c0), "+f"(c1), "+f"(c2), "+f"(c3)
        : "r"(a0), "r"(a1), "r"(a2), "r"(a3), "r"(b0), "r"(b1));
}
__device__ __forceinline__ void ldsm4(uint32_t& r0, uint32_t& r1, uint32_t& r2, uint32_t& r3,
                                      uint32_t addr) {
    asm volatile("ldmatrix.sync.aligned.m8n8.x4.shared.b16 {%0,%1,%2,%3},[%4];"
                 : "=r"(r0), "=r"(r1), "=r"(r2), "=r"(r3) : "r"(addr));
}
__device__ __forceinline__ void ldsm4t(uint32_t& r0, uint32_t& r1, uint32_t& r2, uint32_t& r3,
                                       uint32_t addr) {
    asm volatile("ldmatrix.sync.aligned.m8n8.x4.trans.shared.b16 {%0,%1,%2,%3},[%4];"
                 : "=r"(r0), "=r"(r1), "=r"(r2), "=r"(r3) : "r"(addr));
}

// ---------------- pre-pass: fp32 K/V -> fp16 head-major copy ----------------
__global__ __launch_bounds__(256) void cvt_kv_kernel(const float* __restrict__ qkv) {
    int gid = blockIdx.x * 256 + threadIdx.x;
    int d8 = gid & 15;
    int rest = gid >> 4;
    int s = rest & (Ss - 1);
    int r2 = rest >> 11;
    int h = r2 & (Hh - 1);
    int r3 = r2 >> 5;
    int b = r3 & (Bb - 1);
    int kv = r3 >> 1;
    const float* src = qkv + (((size_t)(b * Ss + s) * 3 + 1 + kv) * Hh + h) * DH + d8 * 8;
    float4 x0 = ((const float4*)src)[0];
    float4 x1 = ((const float4*)src)[1];
    uint4 o;
    o.x = packh2(x0.x, x0.y);
    o.y = packh2(x0.z, x0.w);
    o.z = packh2(x1.x, x1.y);
    o.w = packh2(x1.z, x1.w);
    __half* dst = g_kvh + (((size_t)(kv * Bb + b) * Hh + h) * Ss + s) * DH + d8 * 8;
    *(uint4*)dst = o;
}

// ---------------- main kernel: 8 compute warps + 1 loader warp ----------------
extern __shared__ __align__(16) __half smem_h[];

__global__ __launch_bounds__(288) void fa_f16_ws_kernel(const float* __restrict__ qkv,
                                                        float* __restrict__ out) {
    const int iq   = gridDim.x - 1 - blockIdx.x;
    const int bh   = blockIdx.y;
    const int b    = bh >> 5;
    const int h    = bh & 31;
    const int tid  = threadIdx.x;
    const int warp = tid >> 5;
    const int lane = tid & 31;

    const uint32_t smem_b = s2u(smem_h);
    const uint32_t fullb  = smem_b + BAR_OFF;        // NSTAGE x u64
    const uint32_t emptyb = fullb + NSTAGE * 8;      // NSTAGE x u64

    if (tid == 0) {
#pragma unroll
        for (int i = 0; i < NSTAGE; i++) {
            mbar_init(fullb + i * 8, 1);     // loader lane 0 arrives once per fill
            mbar_init(emptyb + i * 8, 8);    // one arrive per compute warp
        }
    }
    __syncthreads();

    const int HD = Hh * DH;
    const int jmax = 2 * iq + 1;
    const __half* kvb_k = g_kvh + ((size_t)(0 * Bb + b) * Hh + h) * Ss * DH;
    const __half* kvb_v = g_kvh + ((size_t)(1 * Bb + b) * Hh + h) * Ss * DH;

    if (warp == 8) {
        // ---------------- loader warp ----------------
        uint32_t ph = 1;   // producer phase starts 1: first empty-wait passes immediately
        for (int j = 0; j <= jmax; j++) {
            const int s = j & (NSTAGE - 1);
            mbar_wait(emptyb + s * 8, ph);
            const __half* kt = kvb_k + (size_t)j * BN * DH;
            const __half* vt = kvb_v + (size_t)j * BN * DH;
            const uint32_t st = smem_b + s * STAGE_B;
#pragma unroll
            for (int i = 0; i < 32; i++) {
                int c = lane + 32 * i;        // 0..1023 chunks of 16B
                int row = c >> 4;
                int col = (c & 15) * 8;       // halves
                uint32_t off = (uint32_t)(row * KS + col) * 2u;
                cp16(st + off, kt + row * DH + col);
                cp16(st + VOFF_B + off, vt + row * DH + col);
            }
            cp_commit();
            cp_wait<0>();                 // each lane: own copies complete
            __syncwarp();                 // all lanes' copies complete
            if (lane == 0) mbar_arrive(fullb + s * 8);
            if (s == NSTAGE - 1) ph ^= 1;
        }
        return;
    }

    // ---------------- compute warps ----------------
    const int lr = lane >> 2;
    const int lc = lane & 3;
    const int lm = lane >> 3;
    const int lx = lane & 7;

    // scale * log2(e): softmax runs in exp2 domain
    const float scale2 = 0.12751744154134593f;
    const int rowmin = iq * BM + warp * 16;
    const int qr0 = rowmin + lr;
    const int qr1 = qr0 + 8;

    uint32_t qf[8][4];
    {
        const float* q0 = qkv + ((size_t)(b * Ss + qr0) * 3) * HD + h * DH;
        const float* q1 = qkv + ((size_t)(b * Ss + qr1) * 3) * HD + h * DH;
#pragma unroll
        for (int kb = 0; kb < 8; kb++) {
            int d = kb * 16 + 2 * lc;
            float2 x0 = *(const float2*)(q0 + d);
            float2 x1 = *(const float2*)(q1 + d);
            float2 x2 = *(const float2*)(q0 + d + 8);
            float2 x3 = *(const float2*)(q1 + d + 8);
            qf[kb][0] = packh2(x0.x * scale2, x0.y * scale2);
            qf[kb][1] = packh2(x1.x * scale2, x1.y * scale2);
            qf[kb][2] = packh2(x2.x * scale2, x2.y * scale2);
            qf[kb][3] = packh2(x3.x * scale2, x3.y * scale2);
        }
    }

    float O[16][4];
#pragma unroll
    for (int n = 0; n < 16; n++) { O[n][0] = 0.f; O[n][1] = 0.f; O[n][2] = 0.f; O[n][3] = 0.f; }
    float m0 = -1e30f, m1 = -1e30f, l0 = 0.f, l1 = 0.f;

    uint32_t ph = 0;
    for (int j = 0; j <= jmax; j++) {
        const int s = j & (NSTAGE - 1);
        mbar_wait(fullb + s * 8, ph);

        if (j * BN <= rowmin + 15) {
            const uint32_t kbase = smem_b + s * STAGE_B;
            const uint32_t vbase = kbase + VOFF_B;

            // ---- S = Q K^T (exp2-domain logits) ----
            float sacc[8][4];
#pragma unroll
            for (int n = 0; n < 8; n++) { sacc[n][0] = 0.f; sacc[n][1] = 0.f; sacc[n][2] = 0.f; sacc[n][3] = 0.f; }
#pragma unroll
            for (int kb = 0; kb < 8; kb++) {
#pragma unroll
                for (int nbp = 0; nbp < 4; nbp++) {
                    int key = nbp * 16 + (lm >> 1) * 8 + lx;
                    int dim = kb * 16 + (lm & 1) * 8;
                    uint32_t r0, r1, r2, r3;
                    ldsm4(r0, r1, r2, r3, kbase + (uint32_t)(key * KS + dim) * 2u);
                    mma16816(sacc[2*nbp][0], sacc[2*nbp][1], sacc[2*nbp][2], sacc[2*nbp][3],
                             qf[kb][0], qf[kb][1], qf[kb][2], qf[kb][3], r0, r1);
                    mma16816(sacc[2*nbp+1][0], sacc[2*nbp+1][1], sacc[2*nbp+1][2], sacc[2*nbp+1][3],
                             qf[kb][0], qf[kb][1], qf[kb][2], qf[kb][3], r2, r3);
                }
            }

            // ---- causal mask ----
            if ((j + 1) * BN - 1 > rowmin) {
#pragma unroll
                for (int n = 0; n < 8; n++) {
                    int col = j * BN + n * 8 + 2 * lc;
                    if (col     > qr0) sacc[n][0] = -1e30f;
                    if (col + 1 > qr0) sacc[n][1] = -1e30f;
                    if (col     > qr1) sacc[n][2] = -1e30f;
                    if (col + 1 > qr1) sacc[n][3] = -1e30f;
                }
            }

            // ---- online softmax (exp2 domain) ----
            float tm0 = -1e30f, tm1 = -1e30f;
#pragma unroll
            for (int n = 0; n < 8; n++) {
                tm0 = fmaxf(tm0, fmaxf(sacc[n][0], sacc[n][1]));
                tm1 = fmaxf(tm1, fmaxf(sacc[n][2], sacc[n][3]));
            }
            tm0 = fmaxf(tm0, __shfl_xor_sync(0xffffffffu, tm0, 1));
            tm0 = fmaxf(tm0, __shfl_xor_sync(0xffffffffu, tm0, 2));
            tm1 = fmaxf(tm1, __shfl_xor_sync(0xffffffffu, tm1, 1));
            tm1 = fmaxf(tm1, __shfl_xor_sync(0xffffffffu, tm1, 2));

            float mn0 = fmaxf(m0, tm0);
            float mn1 = fmaxf(m1, tm1);
            bool need = (mn0 > m0) || (mn1 > m1);
            float al0 = ex2f(m0 - mn0);
            float al1 = ex2f(m1 - mn1);

            float rs0 = 0.f, rs1 = 0.f;
            uint32_t pf[4][4];
#pragma unroll
            for (int t = 0; t < 4; t++) {
                int n0 = 2 * t, n1 = 2 * t + 1;
                float e00 = ex2f(sacc[n0][0] - mn0);
                float e01 = ex2f(sacc[n0][1] - mn0);
                float e02 = ex2f(sacc[n0][2] - mn1);
                float e03 = ex2f(sacc[n0][3] - mn1);
                float e10 = ex2f(sacc[n1][0] - mn0);
                float e11 = ex2f(sacc[n1][1] - mn0);
                float e12 = ex2f(sacc[n1][2] - mn1);
                float e13 = ex2f(sacc[n1][3] - mn1);
                rs0 += e00 + e01 + e10 + e11;
                rs1 += e02 + e03 + e12 + e13;
                pf[t][0] = packh2(e00, e01);
                pf[t][1] = packh2(e02, e03);
                pf[t][2] = packh2(e10, e11);
                pf[t][3] = packh2(e12, e13);
            }
            rs0 += __shfl_xor_sync(0xffffffffu, rs0, 1);
            rs0 += __shfl_xor_sync(0xffffffffu, rs0, 2);
            rs1 += __shfl_xor_sync(0xffffffffu, rs1, 1);
            rs1 += __shfl_xor_sync(0xffffffffu, rs1, 2);

            l0 = l0 * al0 + rs0;
            l1 = l1 * al1 + rs1;
            m0 = mn0;
            m1 = mn1;

            if (__any_sync(0xffffffffu, need)) {
#pragma unroll
                for (int n = 0; n < 16; n++) {
                    O[n][0] *= al0; O[n][1] *= al0;
                    O[n][2] *= al1; O[n][3] *= al1;
                }
            }

            // ---- O += P V ----
#pragma unroll
            for (int kbv = 0; kbv < 4; kbv++) {
#pragma unroll
                for (int nbp = 0; nbp < 8; nbp++) {
                    int key = kbv * 16 + (lm & 1) * 8 + lx;
                    int dim = nbp * 16 + (lm >> 1) * 8;
                    uint32_t r0, r1, r2, r3;
                    ldsm4t(r0, r1, r2, r3, vbase + (uint32_t)(key * KS + dim) * 2u);
                    mma16816(O[2*nbp][0], O[2*nbp][1], O[2*nbp][2], O[2*nbp][3],
                             pf[kbv][0], pf[kbv][1], pf[kbv][2], pf[kbv][3], r0, r1);
                    mma16816(O[2*nbp+1][0], O[2*nbp+1][1], O[2*nbp+1][2], O[2*nbp+1][3],
                             pf[kbv][0], pf[kbv][1], pf[kbv][2], pf[kbv][3], r2, r3);
                }
            }
        }

        if (lane == 0) mbar_arrive(emptyb + s * 8);
        if (s == NSTAGE - 1) ph ^= 1;
    }

    // ---- epilogue ----
    float inv0 = 1.f / l0;
    float inv1 = 1.f / l1;
    float* ob0 = out + ((size_t)(b * Ss + qr0) * Hh + h) * DH;
    float* ob1 = out + ((size_t)(b * Ss + qr1) * Hh + h) * DH;
#pragma unroll
    for (int n = 0; n < 16; n++) {
        int d = n * 8 + 2 * lc;
        *(float2*)(ob0 + d) = make_float2(O[n][0] * inv0, O[n][1] * inv0);
        *(float2*)(ob1 + d) = make_float2(O[n][2] * inv1, O[n][3] * inv1);
    }
}

extern "C" void kernel_launch(void* const* d_in, const int* in_sizes, int n_in,
                              void* d_out, int out_size) {
    const float* qkv = (const float*)d_in[0];
    (void)in_sizes; (void)n_in; (void)out_size;

    int cvt_blocks = (2 * Bb * Hh * Ss * (DH / 8)) / 256;   // 16384
    cvt_kv_kernel<<<cvt_blocks, 256>>>(qkv);

    const size_t smem_bytes = (size_t)NSTAGE * STAGE_B + 2 * NSTAGE * 8;   // ring + barriers
    cudaFuncSetAttribute(fa_f16_ws_kernel, cudaFuncAttributeMaxDynamicSharedMemorySize,
                         (int)smem_bytes);

    dim3 grid(Ss / BM, Bb * Hh);   // (16, 64)
    fa_f16_ws_kernel<<<grid, 288, smem_bytes>>>(qkv, (float*)d_out);
}